// round 3
// baseline (speedup 1.0000x reference)
#include <cuda_runtime.h>
#include <cuda_bf16.h>

// Per-token head-attention: for each of B*S tokens,
//   scores[h][g] = (q[h] . k[g]) / 8      (H=16, D=64)
//   attn = softmax_g(scores)
//   out[h][d]    = sum_g attn[h][g] * v[g][d]
//   out *= mask[token]
// qkv layout: (B, S, 3, H, D) fp32 contiguous -> per token: q @ +0, k @ +1024, v @ +2048.
// One block (256 threads) per token. Masked tokens write zeros and skip all qkv traffic.
// mask arrives as int32 (harness converts bool_ -> int32).

#define QK_STRIDE 68   // 64 + 4 pad: row r starts at bank (4r mod 32) -> conflict-free tiles

__global__ __launch_bounds__(256, 1) void fa_head_attn_kernel(
    const float* __restrict__ qkv,
    const int* __restrict__ mask,
    float* __restrict__ out)
{
    const int t   = blockIdx.x;
    const int tid = threadIdx.x;

    float* outp = out + (size_t)t * 1024;

    // ---- masked token: write zeros, touch nothing else ----
    if (mask[t] == 0) {
        reinterpret_cast<float4*>(outp)[tid] = make_float4(0.f, 0.f, 0.f, 0.f);
        return;
    }

    __shared__ float sQ[16][QK_STRIDE];
    __shared__ float sK[16][QK_STRIDE];
    __shared__ float sV[16][64];
    __shared__ float sS[16][17];     // stride 17: gcd(17,32)=1 -> row-parallel conflict-free
    __shared__ float sP[16][17];     // un-normalized exp(scores - rowmax)
    __shared__ float sRinv[16];      // 1 / rowsum

    // ---- phase 1: load qkv (768 float4, 3 per thread, fully coalesced) ----
    {
        const float4* src = reinterpret_cast<const float4*>(qkv + (size_t)t * 3072);
        const int r  = tid >> 4;   // 0..15
        const int c4 = tid & 15;   // 0..15
        float4 q4 = src[tid];
        float4 k4 = src[tid + 256];
        float4 v4 = src[tid + 512];
        *reinterpret_cast<float4*>(&sQ[r][c4 * 4]) = q4;
        *reinterpret_cast<float4*>(&sK[r][c4 * 4]) = k4;
        *reinterpret_cast<float4*>(&sV[r][c4 * 4]) = v4;
    }
    __syncthreads();

    // ---- phase 2: scores, 64 threads, 2x2 register tiles ----
    // lane map chosen so each 8-lane LDS phase hits distinct banks:
    //   h0 = 2*((l&3) + 4*w)  -> rows {0,2,4,6}+8w : banks 0/8/16/24 (stride 68)
    //   g0 = 2*(l>>2)         -> <=4 distinct k rows per 8-lane phase
    if (tid < 64) {
        const int w  = tid >> 5;
        const int l  = tid & 31;
        const int h0 = 2 * ((l & 3) + 4 * w);
        const int g0 = 2 * (l >> 2);
        float a00 = 0.f, a01 = 0.f, a10 = 0.f, a11 = 0.f;
        #pragma unroll
        for (int c = 0; c < 16; c++) {
            float4 qa = *reinterpret_cast<const float4*>(&sQ[h0    ][c * 4]);
            float4 qb = *reinterpret_cast<const float4*>(&sQ[h0 + 1][c * 4]);
            float4 ka = *reinterpret_cast<const float4*>(&sK[g0    ][c * 4]);
            float4 kb = *reinterpret_cast<const float4*>(&sK[g0 + 1][c * 4]);
            a00 += qa.x * ka.x + qa.y * ka.y + qa.z * ka.z + qa.w * ka.w;
            a01 += qa.x * kb.x + qa.y * kb.y + qa.z * kb.z + qa.w * kb.w;
            a10 += qb.x * ka.x + qb.y * ka.y + qb.z * ka.z + qb.w * ka.w;
            a11 += qb.x * kb.x + qb.y * kb.y + qb.z * kb.z + qb.w * kb.w;
        }
        const float scale = 0.125f;   // 1/sqrt(64)
        sS[h0    ][g0    ] = a00 * scale;
        sS[h0    ][g0 + 1] = a01 * scale;
        sS[h0 + 1][g0    ] = a10 * scale;
        sS[h0 + 1][g0 + 1] = a11 * scale;
    }
    __syncthreads();

    // ---- phase 3: row softmax (16 threads, one row each) ----
    if (tid < 16) {
        const int h = tid;
        float m = -1e30f;
        #pragma unroll
        for (int g = 0; g < 16; g++) m = fmaxf(m, sS[h][g]);
        float s = 0.f;
        #pragma unroll
        for (int g = 0; g < 16; g++) {
            float e = __expf(sS[h][g] - m);
            sP[h][g] = e;
            s += e;
        }
        sRinv[h] = 1.0f / s;
    }
    __syncthreads();

    // ---- phase 4: out = P * V, 128 threads, 2 heads x 1 float4 per thread ----
    if (tid < 128) {
        const int h0 = 2 * (tid >> 4);
        const int c4 = tid & 15;
        float4 acc0 = make_float4(0.f, 0.f, 0.f, 0.f);
        float4 acc1 = make_float4(0.f, 0.f, 0.f, 0.f);
        #pragma unroll
        for (int g = 0; g < 16; g++) {
            float4 vv = *reinterpret_cast<const float4*>(&sV[g][c4 * 4]);
            float p0 = sP[h0    ][g];
            float p1 = sP[h0 + 1][g];
            acc0.x += p0 * vv.x; acc0.y += p0 * vv.y;
            acc0.z += p0 * vv.z; acc0.w += p0 * vv.w;
            acc1.x += p1 * vv.x; acc1.y += p1 * vv.y;
            acc1.z += p1 * vv.z; acc1.w += p1 * vv.w;
        }
        const float r0 = sRinv[h0];
        const float r1 = sRinv[h0 + 1];
        acc0.x *= r0; acc0.y *= r0; acc0.z *= r0; acc0.w *= r0;
        acc1.x *= r1; acc1.y *= r1; acc1.z *= r1; acc1.w *= r1;
        reinterpret_cast<float4*>(outp)[(h0    ) * 16 + c4] = acc0;
        reinterpret_cast<float4*>(outp)[(h0 + 1) * 16 + c4] = acc1;
    }
}

extern "C" void kernel_launch(void* const* d_in, const int* in_sizes, int n_in,
                              void* d_out, int out_size) {
    const float* qkv  = (const float*)d_in[0];
    const int*   mask = (const int*)d_in[1];
    float*       out  = (float*)d_out;

    // tokens = B*S; qkv has 3*H*D = 3072 floats per token
    const int tokens = in_sizes[0] / 3072;

    fa_head_attn_kernel<<<tokens, 256>>>(qkv, mask, out);
}

// round 4
// speedup vs baseline: 1.0326x; 1.0326x over previous
#include <cuda_runtime.h>
#include <cuda_bf16.h>

// Per-token head-attention over H=16 heads, D=64, for B*S tokens:
//   scores[h][g] = (q[h].k[g]) * 0.125 ; attn = softmax_g ; out[h] = attn @ V ; out *= mask[t]
// qkv: (B,S,3,H,D) fp32 -> per token q @ +0, k @ +1024, v @ +2048.
// One 256-thread block per token; every phase uses all 256 threads.
// mask arrives as int32 (bool_ -> int32 conversion by harness).

#define QK_STRIDE 68   // 64 + 4 pad -> row r base bank = 4r mod 32

__global__ __launch_bounds__(256, 6) void fa_head_attn_kernel(
    const float* __restrict__ qkv,
    const int* __restrict__ mask,
    float* __restrict__ out)
{
    const int t   = blockIdx.x;
    const int tid = threadIdx.x;

    float* outp = out + (size_t)t * 1024;

    // ---- masked token: write zeros, no qkv traffic ----
    if (mask[t] == 0) {
        reinterpret_cast<float4*>(outp)[tid] = make_float4(0.f, 0.f, 0.f, 0.f);
        return;
    }

    __shared__ float sQ[16][QK_STRIDE];
    __shared__ float sK[16][QK_STRIDE];
    __shared__ float sV[16][64];
    __shared__ float sP[16][17];   // exp(scores - rowmax) / rowsum

    // ---- phase 1: load qkv (768 float4, 3 per thread, coalesced) ----
    {
        const float4* src = reinterpret_cast<const float4*>(qkv + (size_t)t * 3072);
        const int r  = tid >> 4;
        const int c4 = tid & 15;
        float4 q4 = src[tid];
        float4 k4 = src[tid + 256];
        float4 v4 = src[tid + 512];
        *reinterpret_cast<float4*>(&sQ[r][c4 * 4]) = q4;
        *reinterpret_cast<float4*>(&sK[r][c4 * 4]) = k4;
        *reinterpret_cast<float4*>(&sV[r][c4 * 4]) = v4;
    }
    __syncthreads();

    // ---- phase 2: one score per thread + register softmax ----
    {
        const int h = tid >> 4;   // 0..15 (2 rows per warp: lanes 0-15 / 16-31)
        const int g = tid & 15;   // 0..15
        float acc = 0.f;
        #pragma unroll
        for (int c = 0; c < 16; c++) {
            float4 qa = *reinterpret_cast<const float4*>(&sQ[h][c * 4]); // broadcast
            float4 ka = *reinterpret_cast<const float4*>(&sK[g][c * 4]); // distinct banks
            acc += qa.x * ka.x + qa.y * ka.y + qa.z * ka.z + qa.w * ka.w;
        }
        // fold 1/sqrt(D) and log2(e) so exp becomes exp2
        const float s = acc * (0.125f * 1.44269504088896340736f);

        // row = 16-lane half-warp: butterfly max then sum
        float m = s;
        #pragma unroll
        for (int d = 8; d >= 1; d >>= 1)
            m = fmaxf(m, __shfl_xor_sync(0xffffffffu, m, d));
        float e = exp2f(s - m);
        float r = e;
        #pragma unroll
        for (int d = 8; d >= 1; d >>= 1)
            r += __shfl_xor_sync(0xffffffffu, r, d);
        sP[h][g] = e * (1.0f / r);   // normalized probability
    }
    __syncthreads();

    // ---- phase 3: out = P @ V, one float4 per thread ----
    {
        const int h  = tid >> 4;
        const int c4 = tid & 15;
        float4 a = make_float4(0.f, 0.f, 0.f, 0.f);
        #pragma unroll
        for (int g = 0; g < 16; g++) {
            float4 vv = *reinterpret_cast<const float4*>(&sV[g][c4 * 4]);
            float p = sP[h][g];      // broadcast within half-warp
            a.x += p * vv.x; a.y += p * vv.y;
            a.z += p * vv.z; a.w += p * vv.w;
        }
        reinterpret_cast<float4*>(outp)[h * 16 + c4] = a;
    }
}

extern "C" void kernel_launch(void* const* d_in, const int* in_sizes, int n_in,
                              void* d_out, int out_size) {
    const float* qkv  = (const float*)d_in[0];
    const int*   mask = (const int*)d_in[1];
    float*       out  = (float*)d_out;

    const int tokens = in_sizes[0] / 3072;   // 3*H*D floats per token

    fa_head_attn_kernel<<<tokens, 256>>>(qkv, mask, out);
}

// round 6
// speedup vs baseline: 1.0745x; 1.0406x over previous
#include <cuda_runtime.h>
#include <cuda_bf16.h>

// Per-token head-attention over H=16 heads, D=64, for B*S tokens:
//   scores[h][g] = (q[h].k[g]) * 0.125 ; attn = softmax_g ; out[h] = attn @ V ; out *= mask[t]
// qkv: (B,S,3,H,D) fp32 -> per token q @ +0, k @ +1024, v @ +2048.
// One 256-thread block per token. mask arrives as int32.
//
// Phase 2: split-D 2x2 register tiling. Warp w owns score rows {2w, 2w+1}.
//   lane l: j=l>>2 -> g0=2j, p=l&3 -> D-slice [16p, 16p+16).
//   Partial 2x2 tiles reduced over p via shfl_xor(1,2); softmax entirely in
//   registers via shfl_xor(4,8,16) row butterflies. No score smem, 2 syncs total.

#define QKS 72   // stride 72: row r base bank = 8r mod 32

__global__ __launch_bounds__(256, 6) void fa_head_attn_kernel(
    const float* __restrict__ qkv,
    const int* __restrict__ mask,
    float* __restrict__ out)
{
    const int t   = blockIdx.x;
    const int tid = threadIdx.x;

    float* outp = out + (size_t)t * 1024;

    // ---- masked token: write zeros, no qkv traffic ----
    if (mask[t] == 0) {
        reinterpret_cast<float4*>(outp)[tid] = make_float4(0.f, 0.f, 0.f, 0.f);
        return;
    }

    __shared__ float sQ[16][QKS];
    __shared__ float sK[16][QKS];
    __shared__ float sV[16][64];
    __shared__ float sP[16][17];   // normalized probabilities

    // ---- phase 1: load qkv (768 float4, 3 per thread, coalesced) ----
    {
        const float4* src = reinterpret_cast<const float4*>(qkv + (size_t)t * 3072);
        const int r  = tid >> 4;
        const int c4 = tid & 15;
        float4 q4 = src[tid];
        float4 k4 = src[tid + 256];
        float4 v4 = src[tid + 512];
        *reinterpret_cast<float4*>(&sQ[r][c4 * 4]) = q4;
        *reinterpret_cast<float4*>(&sK[r][c4 * 4]) = k4;
        *reinterpret_cast<float4*>(&sV[r][c4 * 4]) = v4;
    }
    __syncthreads();

    // ---- phase 2: scores (2x2 tile, D split over 4 lanes) + register softmax ----
    {
        const int l  = tid & 31;
        const int h0 = 2 * (tid >> 5);   // warp -> row pair
        const int g0 = 2 * (l >> 2);     // lane group -> col pair
        const int p  = l & 3;            // D-slice

        float a00 = 0.f, a01 = 0.f, a10 = 0.f, a11 = 0.f;
        #pragma unroll
        for (int i = 0; i < 4; i++) {
            const int off = p * 16 + (((i + p) & 3) << 2);  // rotated c-order: bank-clean
            float4 qa = *reinterpret_cast<const float4*>(&sQ[h0    ][off]);
            float4 qb = *reinterpret_cast<const float4*>(&sQ[h0 + 1][off]);
            float4 ka = *reinterpret_cast<const float4*>(&sK[g0    ][off]);
            float4 kb = *reinterpret_cast<const float4*>(&sK[g0 + 1][off]);
            a00 += qa.x * ka.x + qa.y * ka.y + qa.z * ka.z + qa.w * ka.w;
            a01 += qa.x * kb.x + qa.y * kb.y + qa.z * kb.z + qa.w * kb.w;
            a10 += qb.x * ka.x + qb.y * ka.y + qb.z * ka.z + qb.w * ka.w;
            a11 += qb.x * kb.x + qb.y * kb.y + qb.z * kb.z + qb.w * kb.w;
        }
        // reduce D-partials across the 4 p-lanes
        #pragma unroll
        for (int d = 1; d <= 2; d <<= 1) {
            a00 += __shfl_xor_sync(0xffffffffu, a00, d);
            a01 += __shfl_xor_sync(0xffffffffu, a01, d);
            a10 += __shfl_xor_sync(0xffffffffu, a10, d);
            a11 += __shfl_xor_sync(0xffffffffu, a11, d);
        }
        // fold 1/sqrt(D) and log2(e): softmax via exp2
        const float cs = 0.125f * 1.44269504088896340736f;
        a00 *= cs; a01 *= cs; a10 *= cs; a11 *= cs;

        float m0 = fmaxf(a00, a01);
        float m1 = fmaxf(a10, a11);
        #pragma unroll
        for (int d = 4; d <= 16; d <<= 1) {
            m0 = fmaxf(m0, __shfl_xor_sync(0xffffffffu, m0, d));
            m1 = fmaxf(m1, __shfl_xor_sync(0xffffffffu, m1, d));
        }
        float e00 = exp2f(a00 - m0), e01 = exp2f(a01 - m0);
        float e10 = exp2f(a10 - m1), e11 = exp2f(a11 - m1);
        float s0 = e00 + e01, s1 = e10 + e11;
        #pragma unroll
        for (int d = 4; d <= 16; d <<= 1) {
            s0 += __shfl_xor_sync(0xffffffffu, s0, d);
            s1 += __shfl_xor_sync(0xffffffffu, s1, d);
        }
        const float r0 = 1.0f / s0;
        const float r1 = 1.0f / s1;

        // each p-lane writes one element of the (replicated) 2x2 tile
        float wv = (p == 0) ? e00 * r0
                 : (p == 1) ? e01 * r0
                 : (p == 2) ? e10 * r1
                            : e11 * r1;
        sP[h0 + (p >> 1)][g0 + (p & 1)] = wv;
    }
    __syncthreads();

    // ---- phase 3: out = P @ V, one float4 per thread ----
    {
        const int h  = tid >> 4;
        const int c4 = tid & 15;
        float4 a = make_float4(0.f, 0.f, 0.f, 0.f);
        #pragma unroll
        for (int g = 0; g < 16; g++) {
            float4 vv = *reinterpret_cast<const float4*>(&sV[g][c4 * 4]);
            float p = sP[h][g];   // broadcast within half-warp
            a.x += p * vv.x; a.y += p * vv.y;
            a.z += p * vv.z; a.w += p * vv.w;
        }
        reinterpret_cast<float4*>(outp)[h * 16 + c4] = a;
    }
}

extern "C" void kernel_launch(void* const* d_in, const int* in_sizes, int n_in,
                              void* d_out, int out_size) {
    const float* qkv  = (const float*)d_in[0];
    const int*   mask = (const int*)d_in[1];
    float*       out  = (float*)d_out;

    const int tokens = in_sizes[0] / 3072;   // 3*H*D floats per token

    fa_head_attn_kernel<<<tokens, 256>>>(qkv, mask, out);
}